// round 1
// baseline (speedup 1.0000x reference)
#include <cuda_runtime.h>

// Problem: x (64,112,112,64) f32 NHWC; kernels (3,3,64,64) f32 HWIO (values ±1); beta (64) f32.
// out = conv3x3_SAME( (x-mean)*rsqrt(var+1e-5)+beta , kernels ), mean/var over (N,H,W).

#define N_  64
#define H_  112
#define W_  112
#define C_  64
#define HP  114
#define WP  114
#define M_CNT (N_*H_*W_)              // 802816 elements per channel
#define NVEC  ((size_t)M_CNT * 16)    // total float4 count of x

// Persistent device scratch (zero-initialized .bss; padded borders stay zero forever,
// interior fully rewritten every launch -> deterministic, graph-replay safe).
__device__ __align__(16) float g_xb[(size_t)N_ * HP * WP * C_];
__device__ __align__(16) float g_sum[C_];
__device__ __align__(16) float g_sumsq[C_];
__device__ __align__(16) float g_scale[C_];
__device__ __align__(16) float g_shift[C_];

// ---------------------------------------------------------------------------
__global__ void k_zero_stats() {
    int i = threadIdx.x;
    if (i < C_) { g_sum[i] = 0.0f; g_sumsq[i] = 0.0f; }
}

// ---------------------------------------------------------------------------
// Per-channel sum / sum-of-squares. Thread stride is a multiple of 16 float4s,
// so each thread's float4 lane-group (4 channels) is fixed -> pure register
// accumulation, then shared reduction, then 128 global atomics per block.
__global__ void __launch_bounds__(256) k_stats(const float* __restrict__ x) {
    __shared__ float ssum[C_];
    __shared__ float ssq[C_];
    int tid = threadIdx.x;
    if (tid < C_) { ssum[tid] = 0.0f; ssq[tid] = 0.0f; }
    __syncthreads();

    const float4* xv = (const float4*)x;
    int g = tid & 15;                       // float4 group -> channels 4g..4g+3
    float4 s = make_float4(0.f, 0.f, 0.f, 0.f);
    float4 q = make_float4(0.f, 0.f, 0.f, 0.f);
    size_t stride = (size_t)gridDim.x * blockDim.x;     // multiple of 16
    for (size_t i = (size_t)blockIdx.x * blockDim.x + tid; i < NVEC; i += stride) {
        float4 v = xv[i];
        s.x += v.x; s.y += v.y; s.z += v.z; s.w += v.w;
        q.x += v.x * v.x; q.y += v.y * v.y; q.z += v.z * v.z; q.w += v.w * v.w;
    }
    atomicAdd(&ssum[g * 4 + 0], s.x); atomicAdd(&ssq[g * 4 + 0], q.x);
    atomicAdd(&ssum[g * 4 + 1], s.y); atomicAdd(&ssq[g * 4 + 1], q.y);
    atomicAdd(&ssum[g * 4 + 2], s.z); atomicAdd(&ssq[g * 4 + 2], q.z);
    atomicAdd(&ssum[g * 4 + 3], s.w); atomicAdd(&ssq[g * 4 + 3], q.w);
    __syncthreads();
    if (tid < C_) {
        atomicAdd(&g_sum[tid],   ssum[tid]);
        atomicAdd(&g_sumsq[tid], ssq[tid]);
    }
}

// ---------------------------------------------------------------------------
__global__ void k_finalize(const float* __restrict__ beta) {
    int c = threadIdx.x;
    if (c < C_) {
        const float inv_m = 1.0f / (float)M_CNT;
        float m = g_sum[c] * inv_m;
        float v = g_sumsq[c] * inv_m - m * m;
        float s = rsqrtf(v + 1e-5f);
        g_scale[c] = s;
        g_shift[c] = beta[c] - m * s;
    }
}

// ---------------------------------------------------------------------------
// Fused BN-apply + write into zero-padded buffer (pad = 1 on H and W).
__global__ void __launch_bounds__(256) k_norm(const float* __restrict__ x) {
    __shared__ float4 sc[16];
    __shared__ float4 sh[16];
    int tid = threadIdx.x;
    if (tid < 16) {
        sc[tid] = ((const float4*)g_scale)[tid];
        sh[tid] = ((const float4*)g_shift)[tid];
    }
    __syncthreads();

    const float4* xv = (const float4*)x;
    float4* ov = (float4*)g_xb;
    size_t stride = (size_t)gridDim.x * blockDim.x;
    for (size_t i = (size_t)blockIdx.x * blockDim.x + tid; i < NVEC; i += stride) {
        int g = (int)(i & 15);
        size_t pix = i >> 4;
        int n   = (int)(pix / (H_ * W_));
        int rem = (int)(pix % (H_ * W_));
        int h   = rem / W_;
        int w   = rem % W_;
        float4 v = xv[i];
        float4 s = sc[g];
        float4 b = sh[g];
        v.x = fmaf(v.x, s.x, b.x);
        v.y = fmaf(v.y, s.y, b.y);
        v.z = fmaf(v.z, s.z, b.z);
        v.w = fmaf(v.w, s.w, b.w);
        size_t dst = (((size_t)n * HP + (h + 1)) * WP + (w + 1)) * 16 + g;
        ov[dst] = v;
    }
}

// ---------------------------------------------------------------------------
// Conv 3x3, C_in = C_out = 64. Block = (64 co, 4 pixel-groups) = 256 threads.
// Block tile: one (n, h) row, 28 output columns; thread: 1 co x 7 pixels.
// ci processed in 4 chunks of 16; weights chunk + input tile staged in shared.
__global__ void __launch_bounds__(256) k_conv(const float* __restrict__ kw,
                                              float* __restrict__ out) {
    __shared__ __align__(16) float wsh[144][C_];     // [ (dy*3+dx)*16 + cil ][ co ]
    __shared__ __align__(16) float xs[3][30][16];    // [row][col][cil]

    int co  = threadIdx.x;        // 0..63
    int ty  = threadIdx.y;        // 0..3
    int tid = ty * 64 + co;
    int w0  = blockIdx.x * 28;    // padded col base (== output col base, pad offset cancels)
    int h   = blockIdx.y;
    int n   = blockIdx.z;
    int px0 = ty * 7;

    float acc[7];
#pragma unroll
    for (int p = 0; p < 7; p++) acc[p] = 0.0f;

    for (int cc = 0; cc < 4; cc++) {
        int cc0 = cc * 16;
        __syncthreads();
        // stage weights: 9*16*64 = 9216 floats
        for (int i = tid; i < 9216; i += 256) {
            int t = i >> 6;              // 0..143
            int c = i & 63;
            int dterm = t >> 4;          // dy*3+dx
            int cil   = t & 15;
            wsh[t][c] = kw[((size_t)dterm * 64 + (cc0 + cil)) * 64 + c];
        }
        // stage x tile: 3 rows x 30 cols x 16 ci = 360 float4
        for (int i = tid; i < 360; i += 256) {
            int r   = i / 120;
            int rem = i % 120;
            int col = rem >> 2;
            int cq  = rem & 3;
            const float4* src = (const float4*)&g_xb[
                (((size_t)n * HP + (h + r)) * WP + (w0 + col)) * C_ + cc0 + cq * 4];
            *((float4*)&xs[r][col][cq * 4]) = *src;
        }
        __syncthreads();

#pragma unroll
        for (int dy = 0; dy < 3; dy++) {
#pragma unroll 4
            for (int cil = 0; cil < 16; cil++) {
                float xr[9];
#pragma unroll
                for (int c = 0; c < 9; c++) xr[c] = xs[dy][px0 + c][cil];
#pragma unroll
                for (int dx = 0; dx < 3; dx++) {
                    float w = wsh[(dy * 3 + dx) * 16 + cil][co];
#pragma unroll
                    for (int p = 0; p < 7; p++)
                        acc[p] = fmaf(xr[p + dx], w, acc[p]);
                }
            }
        }
    }

#pragma unroll
    for (int p = 0; p < 7; p++) {
        int w = w0 + px0 + p;
        out[(((size_t)n * H_ + h) * W_ + w) * C_ + co] = acc[p];
    }
}

// ---------------------------------------------------------------------------
extern "C" void kernel_launch(void* const* d_in, const int* in_sizes, int n_in,
                              void* d_out, int out_size) {
    const float* x    = (const float*)d_in[0];
    const float* kw   = (const float*)d_in[1];
    const float* beta = (const float*)d_in[2];
    float* out = (float*)d_out;
    (void)in_sizes; (void)n_in; (void)out_size;

    k_zero_stats<<<1, 64>>>();
    k_stats<<<1024, 256>>>(x);
    k_finalize<<<1, 64>>>(beta);
    k_norm<<<2048, 256>>>(x);

    dim3 bt(64, 4);
    dim3 gr(4, 112, 64);
    k_conv<<<gr, bt>>>(kw, out);
}

// round 3
// speedup vs baseline: 2.4869x; 2.4869x over previous
#include <cuda_runtime.h>
#include <cuda_bf16.h>
#include <cstdint>

// ============================================================================
// x (64,112,112,64) f32 NHWC; kernels (3,3,64,64) f32 HWIO (+-1); beta (64).
// out = conv3x3_SAME(BN_train(x), kernels), fp32.
//
// Path: BN -> padded bf16 hi/lo buffers; conv = implicit GEMM with
// mma.sync.m16n8k16.bf16 (compute_103-legal), persistent CTAs, cp.async
// double-buffered A chunks, B resident in smem.
// ============================================================================

#define N_  64
#define H_  112
#define W_  112
#define C_  64
#define HP  114
#define WP  114
#define M_CNT (N_*H_*W_)
#define NVEC  ((size_t)M_CNT * 16)
#define NPIX  (N_*H_*W_)
#define NTILES (NPIX/128)            // 6272
#define HW_   (H_*W_)                // 12544

// B: [3 dy][192 k][72 pitch] bf16 (pad 64->72 kills ldmatrix bank conflicts)
#define BPITCH 72
#define BROWB  (BPITCH*2)            // 144 bytes
#define BCHUNKB (192*BROWB)          // 27648
#define B_BYTES (3*BCHUNKB)          // 82944

// A: [128 pixels][192 k] bf16, pitch 400B (384 data + 16 pad)
#define APITCH 400
#define ABUFB  (128*APITCH)          // 51200
#define SM_A0  B_BYTES               // 82944 (1024-aligned)
#define CONV_SMEM (B_BYTES + 2*ABUFB)   // 185344

// ---------------- persistent device scratch (zero-init .bss) ----------------
__device__ __align__(16) unsigned short g_xh[(size_t)N_ * HP * WP * C_];
__device__ __align__(16) unsigned short g_xl[(size_t)N_ * HP * WP * C_];
__device__ __align__(16) unsigned short g_wb[3 * 192 * BPITCH];
__device__ float g_sum[C_];
__device__ float g_sumsq[C_];
__device__ float g_scale[C_];
__device__ float g_shift[C_];

// ============================ PTX helpers ===================================
__device__ __forceinline__ uint32_t smem_to_u32(const void* p) {
    uint32_t a;
    asm("{ .reg .u64 t; cvta.to.shared.u64 t, %1; cvt.u32.u64 %0, t; }"
        : "=r"(a) : "l"(p));
    return a;
}

#define LDSM_X4(r, addr) \
    asm volatile("ldmatrix.sync.aligned.m8n8.x4.shared.b16 {%0,%1,%2,%3}, [%4];" \
        : "=r"((r)[0]), "=r"((r)[1]), "=r"((r)[2]), "=r"((r)[3]) : "r"(addr))

#define LDSM_X4_T(r, addr) \
    asm volatile("ldmatrix.sync.aligned.m8n8.x4.trans.shared.b16 {%0,%1,%2,%3}, [%4];" \
        : "=r"((r)[0]), "=r"((r)[1]), "=r"((r)[2]), "=r"((r)[3]) : "r"(addr))

#define MMA16816(c, a, b0v, b1v) \
    asm volatile("mma.sync.aligned.m16n8k16.row.col.f32.bf16.bf16.f32 " \
        "{%0,%1,%2,%3}, {%4,%5,%6,%7}, {%8,%9}, {%0,%1,%2,%3};" \
        : "+f"((c)[0]), "+f"((c)[1]), "+f"((c)[2]), "+f"((c)[3]) \
        : "r"((a)[0]), "r"((a)[1]), "r"((a)[2]), "r"((a)[3]), \
          "r"(b0v), "r"(b1v))

#define CP_ASYNC16(dst_s, src_g) \
    asm volatile("cp.async.cg.shared.global [%0], [%1], 16;" \
        :: "r"(dst_s), "l"(src_g))
#define CP_COMMIT() asm volatile("cp.async.commit_group;" ::: "memory")
#define CP_WAIT0()  asm volatile("cp.async.wait_group 0;" ::: "memory")

__device__ __forceinline__ unsigned short f2bf(float f) {
    __nv_bfloat16 b = __float2bfloat16(f);
    return *reinterpret_cast<unsigned short*>(&b);
}

// ---------------------------------------------------------------------------
__global__ void k_zero_stats() {
    int i = threadIdx.x;
    if (i < C_) { g_sum[i] = 0.0f; g_sumsq[i] = 0.0f; }
}

// ---------------------------------------------------------------------------
__global__ void __launch_bounds__(256) k_stats(const float* __restrict__ x) {
    __shared__ float ssum[C_];
    __shared__ float ssq[C_];
    int tid = threadIdx.x;
    if (tid < C_) { ssum[tid] = 0.0f; ssq[tid] = 0.0f; }
    __syncthreads();

    const float4* xv = (const float4*)x;
    int g = tid & 15;
    float4 s = make_float4(0.f, 0.f, 0.f, 0.f);
    float4 q = make_float4(0.f, 0.f, 0.f, 0.f);
    size_t stride = (size_t)gridDim.x * blockDim.x;
    for (size_t i = (size_t)blockIdx.x * blockDim.x + tid; i < NVEC; i += stride) {
        float4 v = xv[i];
        s.x += v.x; s.y += v.y; s.z += v.z; s.w += v.w;
        q.x += v.x * v.x; q.y += v.y * v.y; q.z += v.z * v.z; q.w += v.w * v.w;
    }
    atomicAdd(&ssum[g * 4 + 0], s.x); atomicAdd(&ssq[g * 4 + 0], q.x);
    atomicAdd(&ssum[g * 4 + 1], s.y); atomicAdd(&ssq[g * 4 + 1], q.y);
    atomicAdd(&ssum[g * 4 + 2], s.z); atomicAdd(&ssq[g * 4 + 2], q.z);
    atomicAdd(&ssum[g * 4 + 3], s.w); atomicAdd(&ssq[g * 4 + 3], q.w);
    __syncthreads();
    if (tid < C_) {
        atomicAdd(&g_sum[tid],   ssum[tid]);
        atomicAdd(&g_sumsq[tid], ssq[tid]);
    }
}

// ---------------------------------------------------------------------------
__global__ void k_finalize(const float* __restrict__ beta) {
    int c = threadIdx.x;
    if (c < C_) {
        const float inv_m = 1.0f / (float)M_CNT;
        float m = g_sum[c] * inv_m;
        float v = g_sumsq[c] * inv_m - m * m;
        float s = rsqrtf(v + 1e-5f);
        g_scale[c] = s;
        g_shift[c] = beta[c] - m * s;
    }
}

// ---------------------------------------------------------------------------
// BN-apply + bf16 hi/lo split into zero-padded buffers.
__global__ void __launch_bounds__(256) k_norm(const float* __restrict__ x) {
    __shared__ float4 sc[16];
    __shared__ float4 sh[16];
    int tid = threadIdx.x;
    if (tid < 16) {
        sc[tid] = ((const float4*)g_scale)[tid];
        sh[tid] = ((const float4*)g_shift)[tid];
    }
    __syncthreads();

    const float4* xv = (const float4*)x;
    uint2* oh = (uint2*)g_xh;
    uint2* ol = (uint2*)g_xl;
    size_t stride = (size_t)gridDim.x * blockDim.x;
    for (size_t i = (size_t)blockIdx.x * blockDim.x + tid; i < NVEC; i += stride) {
        int g = (int)(i & 15);
        size_t pix = i >> 4;
        int n   = (int)(pix / HW_);
        int rem = (int)(pix % HW_);
        int h   = rem / W_;
        int w   = rem % W_;
        float4 v = xv[i];
        float4 s = sc[g];
        float4 b = sh[g];
        v.x = fmaf(v.x, s.x, b.x);
        v.y = fmaf(v.y, s.y, b.y);
        v.z = fmaf(v.z, s.z, b.z);
        v.w = fmaf(v.w, s.w, b.w);

        unsigned short h0 = f2bf(v.x), h1 = f2bf(v.y), h2 = f2bf(v.z), h3 = f2bf(v.w);
        float r0 = v.x - __bfloat162float(*(__nv_bfloat16*)&h0);
        float r1 = v.y - __bfloat162float(*(__nv_bfloat16*)&h1);
        float r2 = v.z - __bfloat162float(*(__nv_bfloat16*)&h2);
        float r3 = v.w - __bfloat162float(*(__nv_bfloat16*)&h3);
        unsigned short l0 = f2bf(r0), l1 = f2bf(r1), l2 = f2bf(r2), l3 = f2bf(r3);

        size_t dpix = ((size_t)n * HP + (h + 1)) * WP + (w + 1);
        size_t u2 = dpix * 16 + g;
        oh[u2] = make_uint2((uint32_t)h0 | ((uint32_t)h1 << 16),
                            (uint32_t)h2 | ((uint32_t)h3 << 16));
        ol[u2] = make_uint2((uint32_t)l0 | ((uint32_t)l1 << 16),
                            (uint32_t)l2 | ((uint32_t)l3 << 16));
    }
}

// ---------------------------------------------------------------------------
// B prep: g_wb[dy][k = dx*64+cin][cout], row pitch 72 bf16.
__global__ void k_wprep(const float* __restrict__ kw) {
    int i = blockIdx.x * blockDim.x + threadIdx.x;
    if (i >= 36864) return;
    int cout = i & 63;
    int cin  = (i >> 6) & 63;
    int t    = i >> 12;            // dy*3+dx
    int dy = t / 3, dx = t % 3;
    float v = kw[((size_t)t * 64 + cin) * 64 + cout];
    g_wb[(size_t)dy * (192 * BPITCH) + (dx * 64 + cin) * BPITCH + cout] = f2bf(v);
}

// ---------------------------------------------------------------------------
// Conv: persistent CTAs, 256 thr (8 warps: 4 m-warps x 2 n-warps).
// Tile = 128 pixels. 6 chunks (dy 0..2 x {hi,lo}), K=192 each.
__global__ void __launch_bounds__(256, 1)
k_conv(float* __restrict__ out) {
    extern __shared__ __align__(1024) unsigned char smem[];
    uint32_t sb = smem_to_u32(smem);
    int tid = threadIdx.x;

    // stage B once (82944 B)
    {
        const uint4* src = (const uint4*)g_wb;
        uint4* dst = (uint4*)smem;
        for (int i = tid; i < B_BYTES / 16; i += 256) dst[i] = src[i];
    }
    __syncthreads();

    int lane = tid & 31;
    int wid  = tid >> 5;
    int mw   = wid >> 1;          // 0..3 -> m = mw*32
    int nw   = wid & 1;           // 0..1 -> n = nw*32
    int sel  = lane >> 3;
    int l7   = lane & 7;

    // per-lane ldmatrix offsets
    uint32_t a_off = (uint32_t)((mw * 32 + (sel & 1) * 8 + l7) * APITCH + (sel >> 1) * 16);
    uint32_t b_off = (uint32_t)(((sel & 1) * 8 + l7) * BROWB + (nw * 32 + (sel >> 1) * 8) * 2);

    int pixl = tid >> 1;          // staging pixel 0..127
    int half = tid & 1;           // staging half (96 bf16 = 192B)

    int first = 1;
    for (int tile = blockIdx.x; tile < NTILES; tile += gridDim.x) {
        int gp  = tile * 128 + pixl;
        int n   = gp / HW_;
        int rem = gp % HW_;
        int h   = rem / W_;
        int w   = rem % W_;
        // byte offset of this pixel's window row (dy=0) + half
        size_t base_b = ((((size_t)n * HP + h) * WP + w) * C_) * 2 + (size_t)half * 192;
        uint32_t dst_b = (uint32_t)(pixl * APITCH + half * 192);

        if (first) {   // prefetch chunk 0 of first tile
            first = 0;
            const char* src = (const char*)g_xh + base_b;
            uint32_t d = sb + SM_A0 + dst_b;
            #pragma unroll
            for (int i = 0; i < 12; i++) CP_ASYNC16(d + i * 16, src + i * 16);
            CP_COMMIT();
        }

        float c[32];
        #pragma unroll
        for (int i = 0; i < 32; i++) c[i] = 0.0f;

        #pragma unroll 1
        for (int j = 0; j < 6; j++) {
            int buf = j & 1;
            int dy  = j >> 1;
            CP_WAIT0();
            __syncthreads();

            // prefetch next chunk (or next tile's chunk 0)
            if (j < 5) {
                int j1 = j + 1;
                const char* srcb = ((j1 & 1) ? (const char*)g_xl : (const char*)g_xh);
                const char* src = srcb + base_b + (size_t)(j1 >> 1) * (WP * C_ * 2);
                uint32_t d = sb + SM_A0 + (buf ^ 1) * ABUFB + dst_b;
                #pragma unroll
                for (int i = 0; i < 12; i++) CP_ASYNC16(d + i * 16, src + i * 16);
                CP_COMMIT();
            } else {
                int t2 = tile + gridDim.x;
                if (t2 < NTILES) {
                    int gp2  = t2 * 128 + pixl;
                    int n2   = gp2 / HW_;
                    int rem2 = gp2 % HW_;
                    int h2   = rem2 / W_;
                    int w2   = rem2 % W_;
                    size_t b2 = ((((size_t)n2 * HP + h2) * WP + w2) * C_) * 2 + (size_t)half * 192;
                    const char* src = (const char*)g_xh + b2;
                    uint32_t d = sb + SM_A0 + dst_b;   // buf0
                    #pragma unroll
                    for (int i = 0; i < 12; i++) CP_ASYNC16(d + i * 16, src + i * 16);
                    CP_COMMIT();
                }
            }

            uint32_t Abase = sb + SM_A0 + buf * ABUFB + a_off;
            uint32_t Bbase = sb + dy * BCHUNKB + b_off;

            #pragma unroll
            for (int s = 0; s < 12; s++) {
                uint32_t ra0[4], ra1[4], rb0[4], rb1[4];
                LDSM_X4(ra0, Abase + s * 32);
                LDSM_X4(ra1, Abase + 16 * APITCH + s * 32);
                LDSM_X4_T(rb0, Bbase + s * (16 * BROWB));
                LDSM_X4_T(rb1, Bbase + s * (16 * BROWB) + 32);

                MMA16816(c +  0, ra0, rb0[0], rb0[1]);
                MMA16816(c +  4, ra0, rb0[2], rb0[3]);
                MMA16816(c +  8, ra0, rb1[0], rb1[1]);
                MMA16816(c + 12, ra0, rb1[2], rb1[3]);
                MMA16816(c + 16, ra1, rb0[0], rb0[1]);
                MMA16816(c + 20, ra1, rb0[2], rb0[3]);
                MMA16816(c + 24, ra1, rb1[0], rb1[1]);
                MMA16816(c + 28, ra1, rb1[2], rb1[3]);
            }
        }

        // epilogue: D frags -> out[pix][cout]
        int r  = lane >> 2;
        int cq = lane & 3;
        size_t obase = (size_t)tile * 128 * 64;
        #pragma unroll
        for (int mf = 0; mf < 2; mf++) {
            int row0 = mw * 32 + mf * 16 + r;
            #pragma unroll
            for (int nf = 0; nf < 4; nf++) {
                int col = nw * 32 + nf * 8 + 2 * cq;
                float* p0 = out + obase + (size_t)row0 * 64 + col;
                *(float2*)p0            = make_float2(c[mf*16 + nf*4 + 0], c[mf*16 + nf*4 + 1]);
                *(float2*)(p0 + 8 * 64) = make_float2(c[mf*16 + nf*4 + 2], c[mf*16 + nf*4 + 3]);
            }
        }
    }
}

// ---------------------------------------------------------------------------
extern "C" void kernel_launch(void* const* d_in, const int* in_sizes, int n_in,
                              void* d_out, int out_size) {
    const float* x    = (const float*)d_in[0];
    const float* kw   = (const float*)d_in[1];
    const float* beta = (const float*)d_in[2];
    float* out = (float*)d_out;
    (void)in_sizes; (void)n_in; (void)out_size;

    cudaFuncSetAttribute(k_conv, cudaFuncAttributeMaxDynamicSharedMemorySize, CONV_SMEM);

    k_zero_stats<<<1, 64>>>();
    k_stats<<<1024, 256>>>(x);
    k_finalize<<<1, 64>>>(beta);
    k_wprep<<<144, 256>>>(kw);
    k_norm<<<2048, 256>>>(x);
    k_conv<<<152, 256, CONV_SMEM>>>(out);
}

// round 4
// speedup vs baseline: 4.3312x; 1.7416x over previous
#include <cuda_runtime.h>
#include <cuda_fp16.h>
#include <cstdint>

// ============================================================================
// x (64,112,112,64) f32 NHWC; kernels (3,3,64,64) f32 HWIO (+-1); beta (64).
// out = conv3x3_SAME(BN_train(x), kernels), fp32.
//
// Numerics: BN output has exactly zero mean / unit variance per channel and
// weights are exactly +-1, so a SINGLE fp16 GEMM gives norm-relative error
// ~2^-12 (=2.4e-4) < 1e-3. Implicit GEMM with mma.sync.m16n8k16.f16,
// persistent CTAs, cp.async double-buffered A, B resident in smem.
// ============================================================================

#define N_  64
#define H_  112
#define W_  112
#define C_  64
#define HP  114
#define WP  114
#define M_CNT (N_*H_*W_)
#define NVEC  ((size_t)M_CNT * 16)
#define NPIX  (N_*H_*W_)
#define NTILES (NPIX/128)            // 6272
#define HW_   (H_*W_)                // 12544

// B: [3 dy][192 k][72 pitch] fp16 (pad 64->72 kills ldmatrix bank conflicts)
#define BPITCH 72
#define BROWB  (BPITCH*2)            // 144 bytes
#define BCHUNKB (192*BROWB)          // 27648
#define B_BYTES (3*BCHUNKB)          // 82944

// A: [128 pixels][192 k] fp16, pitch 400B (384 data + 16 pad)
#define APITCH 400
#define ABUFB  (128*APITCH)          // 51200
#define SM_A0  B_BYTES
#define CONV_SMEM (B_BYTES + 2*ABUFB)   // 185344

// ---------------- persistent device scratch (zero-init .bss) ----------------
__device__ __align__(16) unsigned short g_xf[(size_t)N_ * HP * WP * C_]; // fp16, padded
__device__ __align__(16) unsigned short g_wb[3 * 192 * BPITCH];          // fp16 B image
__device__ float g_sum[C_];
__device__ float g_sumsq[C_];
__device__ float g_scale[C_];
__device__ float g_shift[C_];

// ============================ PTX helpers ===================================
__device__ __forceinline__ uint32_t smem_to_u32(const void* p) {
    uint32_t a;
    asm("{ .reg .u64 t; cvta.to.shared.u64 t, %1; cvt.u32.u64 %0, t; }"
        : "=r"(a) : "l"(p));
    return a;
}

#define LDSM_X4(r, addr) \
    asm volatile("ldmatrix.sync.aligned.m8n8.x4.shared.b16 {%0,%1,%2,%3}, [%4];" \
        : "=r"((r)[0]), "=r"((r)[1]), "=r"((r)[2]), "=r"((r)[3]) : "r"(addr))

#define LDSM_X4_T(r, addr) \
    asm volatile("ldmatrix.sync.aligned.m8n8.x4.trans.shared.b16 {%0,%1,%2,%3}, [%4];" \
        : "=r"((r)[0]), "=r"((r)[1]), "=r"((r)[2]), "=r"((r)[3]) : "r"(addr))

#define MMA16816(c, a, b0v, b1v) \
    asm volatile("mma.sync.aligned.m16n8k16.row.col.f32.f16.f16.f32 " \
        "{%0,%1,%2,%3}, {%4,%5,%6,%7}, {%8,%9}, {%0,%1,%2,%3};" \
        : "+f"((c)[0]), "+f"((c)[1]), "+f"((c)[2]), "+f"((c)[3]) \
        : "r"((a)[0]), "r"((a)[1]), "r"((a)[2]), "r"((a)[3]), \
          "r"(b0v), "r"(b1v))

#define CP_ASYNC16(dst_s, src_g) \
    asm volatile("cp.async.cg.shared.global [%0], [%1], 16;" \
        :: "r"(dst_s), "l"(src_g))
#define CP_COMMIT() asm volatile("cp.async.commit_group;" ::: "memory")
#define CP_WAIT0()  asm volatile("cp.async.wait_group 0;" ::: "memory")

__device__ __forceinline__ unsigned short f2h(float f) {
    __half h = __float2half_rn(f);
    return *reinterpret_cast<unsigned short*>(&h);
}

// ---------------------------------------------------------------------------
__global__ void k_zero_stats() {
    int i = threadIdx.x;
    if (i < C_) { g_sum[i] = 0.0f; g_sumsq[i] = 0.0f; }
}

// ---------------------------------------------------------------------------
__global__ void __launch_bounds__(256) k_stats(const float* __restrict__ x) {
    __shared__ float ssum[C_];
    __shared__ float ssq[C_];
    int tid = threadIdx.x;
    if (tid < C_) { ssum[tid] = 0.0f; ssq[tid] = 0.0f; }
    __syncthreads();

    const float4* xv = (const float4*)x;
    int g = tid & 15;
    float4 s = make_float4(0.f, 0.f, 0.f, 0.f);
    float4 q = make_float4(0.f, 0.f, 0.f, 0.f);
    size_t stride = (size_t)gridDim.x * blockDim.x;
    for (size_t i = (size_t)blockIdx.x * blockDim.x + tid; i < NVEC; i += stride) {
        float4 v = xv[i];
        s.x += v.x; s.y += v.y; s.z += v.z; s.w += v.w;
        q.x += v.x * v.x; q.y += v.y * v.y; q.z += v.z * v.z; q.w += v.w * v.w;
    }
    atomicAdd(&ssum[g * 4 + 0], s.x); atomicAdd(&ssq[g * 4 + 0], q.x);
    atomicAdd(&ssum[g * 4 + 1], s.y); atomicAdd(&ssq[g * 4 + 1], q.y);
    atomicAdd(&ssum[g * 4 + 2], s.z); atomicAdd(&ssq[g * 4 + 2], q.z);
    atomicAdd(&ssum[g * 4 + 3], s.w); atomicAdd(&ssq[g * 4 + 3], q.w);
    __syncthreads();
    if (tid < C_) {
        atomicAdd(&g_sum[tid],   ssum[tid]);
        atomicAdd(&g_sumsq[tid], ssq[tid]);
    }
}

// ---------------------------------------------------------------------------
__global__ void k_finalize(const float* __restrict__ beta) {
    int c = threadIdx.x;
    if (c < C_) {
        const float inv_m = 1.0f / (float)M_CNT;
        float m = g_sum[c] * inv_m;
        float v = g_sumsq[c] * inv_m - m * m;
        float s = rsqrtf(v + 1e-5f);
        g_scale[c] = s;
        g_shift[c] = beta[c] - m * s;
    }
}

// ---------------------------------------------------------------------------
// BN-apply -> fp16 into zero-padded buffer.
__global__ void __launch_bounds__(256) k_norm(const float* __restrict__ x) {
    __shared__ float4 sc[16];
    __shared__ float4 sh[16];
    int tid = threadIdx.x;
    if (tid < 16) {
        sc[tid] = ((const float4*)g_scale)[tid];
        sh[tid] = ((const float4*)g_shift)[tid];
    }
    __syncthreads();

    const float4* xv = (const float4*)x;
    uint2* of = (uint2*)g_xf;
    size_t stride = (size_t)gridDim.x * blockDim.x;
    for (size_t i = (size_t)blockIdx.x * blockDim.x + tid; i < NVEC; i += stride) {
        int g = (int)(i & 15);
        size_t pix = i >> 4;
        int n   = (int)(pix / HW_);
        int rem = (int)(pix % HW_);
        int h   = rem / W_;
        int w   = rem % W_;
        float4 v = xv[i];
        float4 s = sc[g];
        float4 b = sh[g];
        v.x = fmaf(v.x, s.x, b.x);
        v.y = fmaf(v.y, s.y, b.y);
        v.z = fmaf(v.z, s.z, b.z);
        v.w = fmaf(v.w, s.w, b.w);

        unsigned short h0 = f2h(v.x), h1 = f2h(v.y), h2 = f2h(v.z), h3 = f2h(v.w);
        size_t dpix = ((size_t)n * HP + (h + 1)) * WP + (w + 1);
        of[dpix * 16 + g] = make_uint2((uint32_t)h0 | ((uint32_t)h1 << 16),
                                       (uint32_t)h2 | ((uint32_t)h3 << 16));
    }
}

// ---------------------------------------------------------------------------
// B prep: g_wb[dy][k = dx*64+cin][cout], row pitch 72 fp16.
__global__ void k_wprep(const float* __restrict__ kw) {
    int i = blockIdx.x * blockDim.x + threadIdx.x;
    if (i >= 36864) return;
    int cout = i & 63;
    int cin  = (i >> 6) & 63;
    int t    = i >> 12;            // dy*3+dx
    int dy = t / 3, dx = t % 3;
    float v = kw[((size_t)t * 64 + cin) * 64 + cout];
    g_wb[(size_t)dy * (192 * BPITCH) + (dx * 64 + cin) * BPITCH + cout] = f2h(v);
}

// ---------------------------------------------------------------------------
// Conv: persistent CTAs, 256 thr (8 warps: 4 m-warps x 2 n-warps).
// Tile = 128 pixels. 3 chunks (dy 0..2), K=192 fp16 each.
__global__ void __launch_bounds__(256, 1)
k_conv(float* __restrict__ out) {
    extern __shared__ __align__(1024) unsigned char smem[];
    uint32_t sb = smem_to_u32(smem);
    int tid = threadIdx.x;

    // stage B once (82944 B)
    {
        const uint4* src = (const uint4*)g_wb;
        uint4* dst = (uint4*)smem;
        for (int i = tid; i < B_BYTES / 16; i += 256) dst[i] = src[i];
    }
    __syncthreads();

    int lane = tid & 31;
    int wid  = tid >> 5;
    int mw   = wid >> 1;          // 0..3 -> m = mw*32
    int nw   = wid & 1;           // 0..1 -> n = nw*32
    int sel  = lane >> 3;
    int l7   = lane & 7;

    uint32_t a_off = (uint32_t)((mw * 32 + (sel & 1) * 8 + l7) * APITCH + (sel >> 1) * 16);
    uint32_t b_off = (uint32_t)(((sel & 1) * 8 + l7) * BROWB + (nw * 32 + (sel >> 1) * 8) * 2);

    int pixl = tid >> 1;          // staging pixel 0..127
    int half = tid & 1;           // staging half (96 fp16 = 192B)

    const char* gx = (const char*)g_xf;
    uint32_t dst_b = (uint32_t)(pixl * APITCH + half * 192);

    // free-running chunk counter -> smem buffer parity (3 chunks/tile, odd)
    uint32_t jj = 0;

    // prefetch chunk 0 of first tile
    {
        int gp  = blockIdx.x * 128 + pixl;
        int n   = gp / HW_;
        int rem = gp % HW_;
        int h   = rem / W_;
        int w   = rem % W_;
        size_t base_b = ((((size_t)n * HP + h) * WP + w) * C_) * 2 + (size_t)half * 192;
        uint32_t d = sb + SM_A0 + dst_b;        // buf 0
        #pragma unroll
        for (int i = 0; i < 12; i++) CP_ASYNC16(d + i * 16, gx + base_b + i * 16);
        CP_COMMIT();
    }

    for (int tile = blockIdx.x; tile < NTILES; tile += gridDim.x) {
        int gp  = tile * 128 + pixl;
        int n   = gp / HW_;
        int rem = gp % HW_;
        int h   = rem / W_;
        int w   = rem % W_;
        size_t base_b = ((((size_t)n * HP + h) * WP + w) * C_) * 2 + (size_t)half * 192;

        float c[32];
        #pragma unroll
        for (int i = 0; i < 32; i++) c[i] = 0.0f;

        #pragma unroll 1
        for (int j = 0; j < 3; j++) {
            uint32_t buf  = jj & 1;
            uint32_t nbuf = buf ^ 1;
            jj++;
            CP_WAIT0();
            __syncthreads();

            // prefetch next chunk (j+1) or next tile's chunk 0
            if (j < 2) {
                const char* src = gx + base_b + (size_t)(j + 1) * (WP * C_ * 2);
                uint32_t d = sb + SM_A0 + nbuf * ABUFB + dst_b;
                #pragma unroll
                for (int i = 0; i < 12; i++) CP_ASYNC16(d + i * 16, src + i * 16);
                CP_COMMIT();
            } else {
                int t2 = tile + gridDim.x;
                if (t2 < NTILES) {
                    int gp2  = t2 * 128 + pixl;
                    int n2   = gp2 / HW_;
                    int rem2 = gp2 % HW_;
                    int h2   = rem2 / W_;
                    int w2   = rem2 % W_;
                    size_t b2 = ((((size_t)n2 * HP + h2) * WP + w2) * C_) * 2 + (size_t)half * 192;
                    uint32_t d = sb + SM_A0 + nbuf * ABUFB + dst_b;
                    #pragma unroll
                    for (int i = 0; i < 12; i++) CP_ASYNC16(d + i * 16, gx + b2 + i * 16);
                    CP_COMMIT();
                }
            }

            uint32_t Abase = sb + SM_A0 + buf * ABUFB + a_off;
            uint32_t Bbase = sb + j * BCHUNKB + b_off;

            #pragma unroll
            for (int s = 0; s < 12; s++) {
                uint32_t ra0[4], ra1[4], rb0[4], rb1[4];
                LDSM_X4(ra0, Abase + s * 32);
                LDSM_X4(ra1, Abase + 16 * APITCH + s * 32);
                LDSM_X4_T(rb0, Bbase + s * (16 * BROWB));
                LDSM_X4_T(rb1, Bbase + s * (16 * BROWB) + 32);

                MMA16816(c +  0, ra0, rb0[0], rb0[1]);
                MMA16816(c +  4, ra0, rb0[2], rb0[3]);
                MMA16816(c +  8, ra0, rb1[0], rb1[1]);
                MMA16816(c + 12, ra0, rb1[2], rb1[3]);
                MMA16816(c + 16, ra1, rb0[0], rb0[1]);
                MMA16816(c + 20, ra1, rb0[2], rb0[3]);
                MMA16816(c + 24, ra1, rb1[0], rb1[1]);
                MMA16816(c + 28, ra1, rb1[2], rb1[3]);
            }
        }

        // epilogue: D frags -> out[pix][cout]
        int r  = lane >> 2;
        int cq = lane & 3;
        size_t obase = (size_t)tile * 128 * 64;
        #pragma unroll
        for (int mf = 0; mf < 2; mf++) {
            int row0 = mw * 32 + mf * 16 + r;
            #pragma unroll
            for (int nf = 0; nf < 4; nf++) {
                int col = nw * 32 + nf * 8 + 2 * cq;
                float* p0 = out + obase + (size_t)row0 * 64 + col;
                *(float2*)p0            = make_float2(c[mf*16 + nf*4 + 0], c[mf*16 + nf*4 + 1]);
                *(float2*)(p0 + 8 * 64) = make_float2(c[mf*16 + nf*4 + 2], c[mf*16 + nf*4 + 3]);
            }
        }
    }
}

// ---------------------------------------------------------------------------
extern "C" void kernel_launch(void* const* d_in, const int* in_sizes, int n_in,
                              void* d_out, int out_size) {
    const float* x    = (const float*)d_in[0];
    const float* kw   = (const float*)d_in[1];
    const float* beta = (const float*)d_in[2];
    float* out = (float*)d_out;
    (void)in_sizes; (void)n_in; (void)out_size;

    cudaFuncSetAttribute(k_conv, cudaFuncAttributeMaxDynamicSharedMemorySize, CONV_SMEM);

    k_zero_stats<<<1, 64>>>();
    k_stats<<<1024, 256>>>(x);
    k_finalize<<<1, 64>>>(beta);
    k_wprep<<<144, 256>>>(kw);
    k_norm<<<2048, 256>>>(x);
    k_conv<<<152, 256, CONV_SMEM>>>(out);
}

// round 5
// speedup vs baseline: 5.1036x; 1.1783x over previous
#include <cuda_runtime.h>
#include <cuda_fp16.h>
#include <cstdint>

// ============================================================================
// x (64,112,112,64) f32 NHWC; kernels (3,3,64,64) f32 HWIO (+-1); beta (64).
// out = conv3x3_SAME(BN_train(x), kernels), fp32.
//
// BN folded into the GEMM: out = conv(fp16(x_raw), w*s_ci) + bias_co, with
// padded border filled with fp16(-shift/scale) so padded taps contribute
// exactly -w*shift (absorbed into bias_co = sum_{9,ci} w*shift_ci).
// Conv = implicit GEMM mma.sync.m16n8k16.f16, persistent CTAs, warp-owned
// double-buffered A staging (cp.async, NO block barriers in main loop).
// ============================================================================

#define N_  64
#define H_  112
#define W_  112
#define C_  64
#define HP  114
#define WP  114
#define M_CNT (N_*H_*W_)
#define NVEC  ((size_t)M_CNT * 16)
#define NPIX  (N_*H_*W_)
#define NTILES (NPIX/128)            // 6272
#define HW_   (H_*W_)                // 12544
#define PIXB  (C_*2)                 // 128 bytes per padded pixel
#define ROWB  (WP*PIXB)              // 14592 bytes per padded row

// B: [3 dy][192 k][72 pitch] fp16
#define BPITCH 72
#define BROWB  (BPITCH*2)            // 144
#define BCHUNKB (192*BROWB)          // 27648
#define B_BYTES (3*BCHUNKB)          // 82944

// A: per-warp [16 pixels][192 k] fp16, pitch 400B, double buffered
#define APITCH 400
#define AWBUF  (16*APITCH)           // 6400
#define SM_A0  B_BYTES
#define CONV_SMEM (B_BYTES + 8*2*AWBUF)   // 185344

// ---------------- persistent device scratch (zero-init .bss) ----------------
__device__ __align__(16) unsigned short g_xf[(size_t)N_ * HP * WP * C_]; // fp16 raw x, padded
__device__ __align__(16) unsigned short g_wb[3 * 192 * BPITCH];          // fp16 w*s image
__device__ float g_sum[C_];
__device__ float g_sumsq[C_];
__device__ float g_scale[C_];
__device__ float g_shift[C_];
__device__ float g_bias[C_];
__device__ unsigned short g_bord[C_];

// ============================ PTX helpers ===================================
__device__ __forceinline__ uint32_t smem_to_u32(const void* p) {
    uint32_t a;
    asm("{ .reg .u64 t; cvta.to.shared.u64 t, %1; cvt.u32.u64 %0, t; }"
        : "=r"(a) : "l"(p));
    return a;
}

#define LDSM_X4(r, addr) \
    asm volatile("ldmatrix.sync.aligned.m8n8.x4.shared.b16 {%0,%1,%2,%3}, [%4];" \
        : "=r"((r)[0]), "=r"((r)[1]), "=r"((r)[2]), "=r"((r)[3]) : "r"(addr))

#define LDSM_X4_T(r, addr) \
    asm volatile("ldmatrix.sync.aligned.m8n8.x4.trans.shared.b16 {%0,%1,%2,%3}, [%4];" \
        : "=r"((r)[0]), "=r"((r)[1]), "=r"((r)[2]), "=r"((r)[3]) : "r"(addr))

#define MMA16816(c, a, b0v, b1v) \
    asm volatile("mma.sync.aligned.m16n8k16.row.col.f32.f16.f16.f32 " \
        "{%0,%1,%2,%3}, {%4,%5,%6,%7}, {%8,%9}, {%0,%1,%2,%3};" \
        : "+f"((c)[0]), "+f"((c)[1]), "+f"((c)[2]), "+f"((c)[3]) \
        : "r"((a)[0]), "r"((a)[1]), "r"((a)[2]), "r"((a)[3]), \
          "r"(b0v), "r"(b1v))

#define CP_ASYNC16(dst_s, src_g) \
    asm volatile("cp.async.cg.shared.global [%0], [%1], 16;" \
        :: "r"(dst_s), "l"(src_g))
#define CP_COMMIT() asm volatile("cp.async.commit_group;" ::: "memory")
#define CP_WAIT0()  asm volatile("cp.async.wait_group 0;" ::: "memory")
#define CP_WAIT1()  asm volatile("cp.async.wait_group 1;" ::: "memory")

__device__ __forceinline__ unsigned short f2h(float f) {
    __half h = __float2half_rn(f);
    return *reinterpret_cast<unsigned short*>(&h);
}

// ---------------------------------------------------------------------------
__global__ void k_zero_stats() {
    int i = threadIdx.x;
    if (i < C_) { g_sum[i] = 0.0f; g_sumsq[i] = 0.0f; }
}

// ---------------------------------------------------------------------------
// Fused: per-channel moments of x + raw-x fp16 conversion into padded buffer.
__global__ void __launch_bounds__(256) k_stats_conv(const float* __restrict__ x) {
    __shared__ float ssum[C_];
    __shared__ float ssq[C_];
    int tid = threadIdx.x;
    if (tid < C_) { ssum[tid] = 0.0f; ssq[tid] = 0.0f; }
    __syncthreads();

    const float4* xv = (const float4*)x;
    uint2* of = (uint2*)g_xf;
    int g = tid & 15;
    float4 s = make_float4(0.f, 0.f, 0.f, 0.f);
    float4 q = make_float4(0.f, 0.f, 0.f, 0.f);
    size_t stride = (size_t)gridDim.x * blockDim.x;     // multiple of 16
    for (size_t i = (size_t)blockIdx.x * blockDim.x + tid; i < NVEC; i += stride) {
        float4 v = xv[i];
        s.x += v.x; s.y += v.y; s.z += v.z; s.w += v.w;
        q.x += v.x * v.x; q.y += v.y * v.y; q.z += v.z * v.z; q.w += v.w * v.w;

        size_t pix = i >> 4;
        int n   = (int)(pix / HW_);
        int rem = (int)(pix % HW_);
        int h   = rem / W_;
        int w   = rem % W_;
        unsigned short h0 = f2h(v.x), h1 = f2h(v.y), h2 = f2h(v.z), h3 = f2h(v.w);
        size_t dpix = ((size_t)n * HP + (h + 1)) * WP + (w + 1);
        of[dpix * 16 + g] = make_uint2((uint32_t)h0 | ((uint32_t)h1 << 16),
                                       (uint32_t)h2 | ((uint32_t)h3 << 16));
    }
    atomicAdd(&ssum[g * 4 + 0], s.x); atomicAdd(&ssq[g * 4 + 0], q.x);
    atomicAdd(&ssum[g * 4 + 1], s.y); atomicAdd(&ssq[g * 4 + 1], q.y);
    atomicAdd(&ssum[g * 4 + 2], s.z); atomicAdd(&ssq[g * 4 + 2], q.z);
    atomicAdd(&ssum[g * 4 + 3], s.w); atomicAdd(&ssq[g * 4 + 3], q.w);
    __syncthreads();
    if (tid < C_) {
        atomicAdd(&g_sum[tid],   ssum[tid]);
        atomicAdd(&g_sumsq[tid], ssq[tid]);
    }
}

// ---------------------------------------------------------------------------
__global__ void k_finalize(const float* __restrict__ beta) {
    int c = threadIdx.x;
    if (c < C_) {
        const float inv_m = 1.0f / (float)M_CNT;
        float m = g_sum[c] * inv_m;
        float v = g_sumsq[c] * inv_m - m * m;
        float s = rsqrtf(v + 1e-5f);
        float sh = beta[c] - m * s;
        g_scale[c] = s;
        g_shift[c] = sh;
        g_bord[c]  = f2h(-sh / s);     // padded border value in raw-x domain
    }
}

// ---------------------------------------------------------------------------
// Fill padded border pixels with per-channel g_bord (re-done every launch).
__global__ void __launch_bounds__(256) k_border() {
    int idx = blockIdx.x * blockDim.x + threadIdx.x;   // (img, border_pix, group4)
    if (idx >= 64 * 452 * 16) return;
    int g   = idx & 15;
    int bp  = (idx >> 4) % 452;
    int img = (idx >> 4) / 452;
    int h, w;
    if (bp < 114)      { h = 0;   w = bp; }
    else if (bp < 228) { h = 113; w = bp - 114; }
    else { int j = bp - 228; h = 1 + (j >> 1); w = (j & 1) ? 113 : 0; }
    const unsigned short* bd = g_bord;
    uint32_t v0 = (uint32_t)bd[g*4+0] | ((uint32_t)bd[g*4+1] << 16);
    uint32_t v1 = (uint32_t)bd[g*4+2] | ((uint32_t)bd[g*4+3] << 16);
    ((uint2*)g_xf)[(((size_t)img * HP + h) * WP + w) * 16 + g] = make_uint2(v0, v1);
}

// ---------------------------------------------------------------------------
// B prep: g_wb[dy][k = dx*64+cin][cout] = fp16( w * scale[cin] ), pitch 72.
__global__ void k_wprep(const float* __restrict__ kw) {
    int i = blockIdx.x * blockDim.x + threadIdx.x;
    if (i >= 36864) return;
    int cout = i & 63;
    int cin  = (i >> 6) & 63;
    int t    = i >> 12;            // dy*3+dx
    int dy = t / 3, dx = t % 3;
    float v = kw[((size_t)t * 64 + cin) * 64 + cout] * g_scale[cin];
    g_wb[(size_t)dy * (192 * BPITCH) + (dx * 64 + cin) * BPITCH + cout] = f2h(v);
}

// ---------------------------------------------------------------------------
// bias[co] = sum_{t,ci} w[t,ci,co] * shift[ci]
__global__ void k_bias(const float* __restrict__ kw) {
    int co = threadIdx.x;
    if (co >= C_) return;
    float acc = 0.0f;
    for (int t = 0; t < 9; t++)
        for (int ci = 0; ci < 64; ci++)
            acc += kw[((size_t)t * 64 + ci) * 64 + co] * g_shift[ci];
    g_bias[co] = acc;
}

// ---------------------------------------------------------------------------
// Conv: persistent CTAs, 256 thr = 8 warps, warp tile 16 pixels x 64 cout.
// No block barriers in the main loop: each warp owns its A staging region.
__global__ void __launch_bounds__(256, 1)
k_conv(float* __restrict__ out) {
    extern __shared__ __align__(1024) unsigned char smem[];
    uint32_t sb = smem_to_u32(smem);
    int tid = threadIdx.x;

    // stage B once
    {
        const uint4* src = (const uint4*)g_wb;
        uint4* dst = (uint4*)smem;
        for (int i = tid; i < B_BYTES / 16; i += 256) dst[i] = src[i];
    }
    __syncthreads();

    int lane = tid & 31;
    int wid  = tid >> 5;
    int sel  = lane >> 3;
    int l7   = lane & 7;

    uint32_t awbase = sb + SM_A0 + (uint32_t)wid * (2 * AWBUF);
    uint32_t a_off  = awbase + (uint32_t)(((sel & 1) * 8 + l7) * APITCH + (sel >> 1) * 16);
    uint32_t b_base = sb + (uint32_t)(((sel & 1) * 8 + l7) * BROWB + ((sel >> 1) * 8) * 2);

    int p_local = lane >> 1;       // 0..15
    int half    = lane & 1;
    uint32_t dst_off = (uint32_t)(p_local * APITCH + half * 192);
    const char* gx = (const char*)g_xf;

    // per-lane bias registers (two cols per n-slice)
    int cq = lane & 3;
    float bia0[8], bia1[8];
    #pragma unroll
    for (int nsl = 0; nsl < 8; nsl++) {
        bia0[nsl] = g_bias[nsl * 8 + 2 * cq];
        bia1[nsl] = g_bias[nsl * 8 + 2 * cq + 1];
    }

    uint32_t jj = 0;               // free-running chunk counter (buffer parity)

    // prologue: prefetch (first tile, dy=0) into buf 0
    {
        int gp  = blockIdx.x * 128 + wid * 16 + p_local;
        int n   = gp / HW_;
        int rem = gp % HW_;
        int h   = rem / W_;
        int w   = rem % W_;
        const char* src = gx + (((size_t)n * HP + h) * WP + w) * PIXB + half * 192;
        uint32_t d = awbase + dst_off;
        #pragma unroll
        for (int i = 0; i < 12; i++) CP_ASYNC16(d + i * 16, src + i * 16);
        CP_COMMIT();
    }

    for (int tile = blockIdx.x; tile < NTILES; tile += gridDim.x) {
        int gp  = tile * 128 + wid * 16 + p_local;
        int n   = gp / HW_;
        int rem = gp % HW_;
        int h   = rem / W_;
        int w   = rem % W_;
        const char* base = gx + (((size_t)n * HP + h) * WP + w) * PIXB + half * 192;

        float c[32];
        #pragma unroll
        for (int i = 0; i < 32; i++) c[i] = 0.0f;

        #pragma unroll 1
        for (int j = 0; j < 3; j++) {
            uint32_t buf  = jj & 1;
            uint32_t nbuf = buf ^ 1;
            jj++;

            // prefetch next chunk (distance 1), then wait for current
            if (j < 2) {
                const char* src = base + (size_t)(j + 1) * ROWB;
                uint32_t d = awbase + nbuf * AWBUF + dst_off;
                #pragma unroll
                for (int i = 0; i < 12; i++) CP_ASYNC16(d + i * 16, src + i * 16);
                CP_COMMIT();
                CP_WAIT1();
            } else {
                int t2 = tile + gridDim.x;
                if (t2 < NTILES) {
                    int gp2  = t2 * 128 + wid * 16 + p_local;
                    int n2   = gp2 / HW_;
                    int rem2 = gp2 % HW_;
                    int h2   = rem2 / W_;
                    int w2   = rem2 % W_;
                    const char* src = gx + (((size_t)n2 * HP + h2) * WP + w2) * PIXB + half * 192;
                    uint32_t d = awbase + nbuf * AWBUF + dst_off;
                    #pragma unroll
                    for (int i = 0; i < 12; i++) CP_ASYNC16(d + i * 16, src + i * 16);
                    CP_COMMIT();
                    CP_WAIT1();
                } else {
                    CP_WAIT0();
                }
            }
            __syncwarp();

            uint32_t Abase = a_off + buf * AWBUF;
            uint32_t Bbase = b_base + j * BCHUNKB;

            #pragma unroll
            for (int s = 0; s < 12; s++) {
                uint32_t ra[4], rb0[4], rb1[4], rb2[4], rb3[4];
                LDSM_X4(ra, Abase + s * 32);
                uint32_t Bs = Bbase + s * (16 * BROWB);
                LDSM_X4_T(rb0, Bs);
                LDSM_X4_T(rb1, Bs + 32);
                LDSM_X4_T(rb2, Bs + 64);
                LDSM_X4_T(rb3, Bs + 96);

                MMA16816(c +  0, ra, rb0[0], rb0[1]);
                MMA16816(c +  4, ra, rb0[2], rb0[3]);
                MMA16816(c +  8, ra, rb1[0], rb1[1]);
                MMA16816(c + 12, ra, rb1[2], rb1[3]);
                MMA16816(c + 16, ra, rb2[0], rb2[1]);
                MMA16816(c + 20, ra, rb2[2], rb2[3]);
                MMA16816(c + 24, ra, rb3[0], rb3[1]);
                MMA16816(c + 28, ra, rb3[2], rb3[3]);
            }
        }

        // epilogue: add bias, store
        int r = lane >> 2;
        int pix0 = tile * 128 + wid * 16 + r;
        float* o0 = out + (size_t)pix0 * 64 + 2 * cq;
        float* o1 = o0 + 8 * 64;
        #pragma unroll
        for (int nsl = 0; nsl < 8; nsl++) {
            *(float2*)(o0 + nsl * 8) = make_float2(c[nsl*4+0] + bia0[nsl],
                                                   c[nsl*4+1] + bia1[nsl]);
            *(float2*)(o1 + nsl * 8) = make_float2(c[nsl*4+2] + bia0[nsl],
                                                   c[nsl*4+3] + bia1[nsl]);
        }
    }
}

// ---------------------------------------------------------------------------
extern "C" void kernel_launch(void* const* d_in, const int* in_sizes, int n_in,
                              void* d_out, int out_size) {
    const float* x    = (const float*)d_in[0];
    const float* kw   = (const float*)d_in[1];
    const float* beta = (const float*)d_in[2];
    float* out = (float*)d_out;
    (void)in_sizes; (void)n_in; (void)out_size;

    cudaFuncSetAttribute(k_conv, cudaFuncAttributeMaxDynamicSharedMemorySize, CONV_SMEM);

    k_zero_stats<<<1, 64>>>();
    k_stats_conv<<<2048, 256>>>(x);
    k_finalize<<<1, 64>>>(beta);
    k_border<<<(64 * 452 * 16 + 255) / 256, 256>>>();
    k_wprep<<<144, 256>>>(kw);
    k_bias<<<1, 64>>>(kw);
    k_conv<<<152, 256, CONV_SMEM>>>(out);
}